// round 8
// baseline (speedup 1.0000x reference)
#include <cuda_runtime.h>

// ---------------- problem constants ----------------
#define Bq   256
#define Tq   128
#define AD   8
#define ZD   32
#define KM   16
#define HIDq 50
#define BT   (Bq*Tq)

// ---------------- device scratch ----------------
__device__ float g_w[BT*KM];
__device__ float g_sigf[(size_t)BT*1024];   // Sigma_f[t]
__device__ float g_T1s[(size_t)BT*1024];    // T1 = A_{t+1} Sigma_f[t]   (slot t, t<=T-2)
__device__ float g_sp[(size_t)BT*1024];     // Sigma_pred[t+1]           (slot t, t<=T-2)
__device__ float g_X[(size_t)BT*1024];      // X = sp^{-1} T1 (= J^T)    (slot t, t<=T-2)
__device__ float g_muf[BT*ZD];              // mu_f[t]
__device__ float g_mp[BT*ZD];               // mu_pred[t+1]              (slot t, t<=T-2)

// =====================================================================
// Kernel 1: LSTM over T + softmax mixture weights (round-6 verified).
// =====================================================================
__global__ void __launch_bounds__(256)
lstm_kernel(const float* __restrict__ a,  const float* __restrict__ a1,
            const float* __restrict__ W_ih, const float* __restrict__ W_hh,
            const float* __restrict__ b_ih, const float* __restrict__ b_hh,
            const float* __restrict__ W_alpha, const float* __restrict__ b_alpha)
{
    __shared__ float sWhh[HIDq*200];     // transposed: [j][g]
    __shared__ float sWa[KM*HIDq];
    __shared__ float sh[HIDq], sc[HIDq], sx[AD], sg[200];

    const int b = blockIdx.x, tid = threadIdx.x;

    float wi[AD]; float bg = 0.f;
    if (tid < 200) {
        #pragma unroll
        for (int j = 0; j < AD; j++) wi[j] = W_ih[tid*AD + j];
        bg = b_ih[tid] + b_hh[tid];
    }
    for (int i = tid; i < 200*HIDq; i += 256) {
        int g = i / HIDq, j = i % HIDq;
        sWhh[j*200 + g] = W_hh[i];
    }
    for (int i = tid; i < KM*HIDq; i += 256) sWa[i] = W_alpha[i];
    if (tid < HIDq) { sh[tid] = 0.f; sc[tid] = 0.f; }
    __syncthreads();

    for (int t = 0; t < Tq; t++) {
        if (tid < AD) sx[tid] = (t == 0) ? a1[tid] : a[(b*Tq + (t-1))*AD + tid];
        __syncthreads();                 // B1
        if (tid < 200) {
            float a0 = bg, a1_ = 0.f, a2 = 0.f, a3 = 0.f;
            #pragma unroll
            for (int j = 0; j < AD; j++) a0 += sx[j]*wi[j];
            #pragma unroll
            for (int j = 0; j < 48; j += 4) {
                a0  += sh[j  ]*sWhh[(j  )*200 + tid];
                a1_ += sh[j+1]*sWhh[(j+1)*200 + tid];
                a2  += sh[j+2]*sWhh[(j+2)*200 + tid];
                a3  += sh[j+3]*sWhh[(j+3)*200 + tid];
            }
            a0  += sh[48]*sWhh[48*200 + tid];
            a1_ += sh[49]*sWhh[49*200 + tid];
            sg[tid] = (a0 + a1_) + (a2 + a3);
        }
        __syncthreads();                 // B2
        if (tid < HIDq) {
            float ig = 1.f/(1.f + __expf(-sg[tid]));
            float fg = 1.f/(1.f + __expf(-sg[HIDq + tid]));
            float gg = tanhf(sg[2*HIDq + tid]);
            float og = 1.f/(1.f + __expf(-sg[3*HIDq + tid]));
            float c  = fg*sc[tid] + ig*gg;
            sc[tid] = c;
            sh[tid] = og*tanhf(c);
        }
        __syncthreads();                 // B3
        if (tid < 32) {
            float logit = -1e30f;
            if (tid < KM) {
                logit = b_alpha[tid];
                #pragma unroll
                for (int j = 0; j < HIDq; j++) logit += sh[j]*sWa[tid*HIDq + j];
            }
            float m = logit;
            #pragma unroll
            for (int d = 8; d; d >>= 1)
                m = fmaxf(m, __shfl_xor_sync(0xffffffffu, m, d, 16));
            float e = __expf(logit - m);
            float s = e;
            #pragma unroll
            for (int d = 8; d; d >>= 1)
                s += __shfl_xor_sync(0xffffffffu, s, d, 16);
            if (tid < KM) g_w[(b*Tq + t)*KM + tid] = e/s;
        }
    }
}

// =====================================================================
// Kernel 2: A_t/C_t mixing (verified, unchanged).
// =====================================================================
__global__ void __launch_bounds__(256)
mix_kernel(const float* __restrict__ Ag, const float* __restrict__ Cg,
           float* __restrict__ outA, float* __restrict__ outC)
{
    __shared__ float sw[128*KM];
    const int tid = threadIdx.x;
    const int r0  = blockIdx.x * 128;
    for (int i = tid; i < 128*KM; i += 256) sw[i] = g_w[r0*KM + i];
    __syncthreads();

    for (int c = tid; c < 1280; c += 256) {
        float av[KM];
        if (c < 1024) {
            #pragma unroll
            for (int k = 0; k < KM; k++) av[k] = Ag[k*1024 + c];
            for (int r = 0; r < 128; r++) {
                float acc = 0.f;
                #pragma unroll
                for (int k = 0; k < KM; k++) acc += sw[r*KM + k]*av[k];
                outA[(size_t)(r0 + r)*1024 + c] = acc;
            }
        } else {
            const int cc = c - 1024;
            #pragma unroll
            for (int k = 0; k < KM; k++) av[k] = Cg[k*256 + cc];
            for (int r = 0; r < 128; r++) {
                float acc = 0.f;
                #pragma unroll
                for (int k = 0; k < KM; k++) acc += sw[r*KM + k]*av[k];
                outC[(r0 + r)*256 + cc] = acc;
            }
        }
    }
}

// =====================================================================
// Kernel 3: Kalman forward filter.
// Pt computation RESTORED (round-6 verified form — Kg MUST come from
// Pt = rows of sigp, not M1 = cols; the M1 substitution feeds the
// unstable antisymmetric mode and NaNs). Pass6/pass7 register-tiled.
// =====================================================================
__global__ void __launch_bounds__(256)
fwd_kernel(const float* __restrict__ a,
           float* __restrict__ out_mu, float* __restrict__ out_sig,
           const float* __restrict__ outA, const float* __restrict__ outC)
{
    __shared__ float sAbuf[2*1056];                 // ping-pong A (stride 33)
    __shared__ float sC[256];                       // C_t [8][32]
    __shared__ float sigp[1056];                    // sig_pred (stride 33)
    __shared__ __align__(16) float sigf[1024];      // sig_filt (stride 32)
    __shared__ float big[1024];                     // M1 | Pt | KgT | aug8
    __shared__ __align__(16) float T1b[32*36];      // T1 (stride 36)
    __shared__ float sAmu[ZD], serr[AD], smu[ZD];

    const int b = blockIdx.x, tid = threadIdx.x;
    const int i4 = tid >> 3;                // tiled-output row (0..31)
    const int jb = (tid & 7) << 2;          // tiled-output col block (x4)

    // ---- init: sig_pred = 20*I, mu = 0, load A_t[b][0] ----
    for (int e = tid; e < 1024; e += 256) {
        int i = e >> 5, j = e & 31;
        sigp[i*33 + j] = (i == j) ? 20.f : 0.f;
        sAbuf[i*33 + j] = outA[(size_t)(b*Tq)*1024 + e];
    }
    if (tid < ZD) smu[tid] = 0.f;
    __syncthreads();

    for (int t = 0; t < Tq; t++) {
        float* Ac  = sAbuf + (t & 1)*1056;
        float* Anx = sAbuf + ((t + 1) & 1)*1056;
        const int btt = b*Tq + t;

        sC[tid] = outC[(size_t)btt*256 + tid];
        __syncthreads();

        // M1 = C @ sigp (8x32) ; Pt[l][i] = (sigp C^T)[i][l] (round-6 verified)
        {
            int l = tid >> 5, j = tid & 31;
            float acc = 0.f;
            #pragma unroll
            for (int m = 0; m < 32; m++) acc += sC[l*32 + m]*sigp[m*33 + j];
            big[l*32 + j] = acc;
            int i = tid & 31, l2 = tid >> 5;
            float acc2 = 0.f;
            #pragma unroll
            for (int m = 0; m < 32; m++) acc2 += sigp[i*33 + m]*sC[l2*32 + m];
            big[256 + l2*32 + i] = acc2;
        }
        __syncthreads();

        // S = M1 @ C^T + R  ->  augmented [S | I] at big+768 (8x16)
        if (tid < 64) {
            int l = tid >> 3, n = tid & 7;
            float acc = 0.f;
            #pragma unroll
            for (int m = 0; m < 32; m++) acc += big[l*32 + m]*sC[n*32 + m];
            big[768 + l*16 + n]     = acc + ((l == n) ? 0.03f : 0.f);
            big[768 + l*16 + 8 + n] = (l == n) ? 1.f : 0.f;
        }
        __syncthreads();

        // invert 8x8 SPD (Gauss-Jordan, warp 0 only, verified)
        if (tid < 32) {
            int r = tid >> 2, c0 = (tid & 3)*4;
            #pragma unroll
            for (int p = 0; p < 8; p++) {
                float fc  = big[768 + r*16 + p];
                float p0 = big[768 + p*16 + c0];
                float p1 = big[768 + p*16 + c0 + 1];
                float p2 = big[768 + p*16 + c0 + 2];
                float p3 = big[768 + p*16 + c0 + 3];
                float pd = big[768 + p*16 + p];
                __syncwarp();
                float pinv = 1.f/pd;
                if (r == p) {
                    big[768 + r*16 + c0]     = p0*pinv;
                    big[768 + r*16 + c0 + 1] = p1*pinv;
                    big[768 + r*16 + c0 + 2] = p2*pinv;
                    big[768 + r*16 + c0 + 3] = p3*pinv;
                } else {
                    float f = fc*pinv;
                    big[768 + r*16 + c0]     -= f*p0;
                    big[768 + r*16 + c0 + 1] -= f*p1;
                    big[768 + r*16 + c0 + 2] -= f*p2;
                    big[768 + r*16 + c0 + 3] -= f*p3;
                }
                __syncwarp();
            }
        }
        __syncthreads();

        // Kg^T[l][i] = sum_n Pt[n][i] * Sinv[n][l]   (at 512 + l*32 + i)
        // (round-6 verified: reads Pt at big[256 + n*32 + i])
        {
            int l = tid >> 5, i = tid & 31;
            float acc = 0.f;
            #pragma unroll
            for (int n = 0; n < 8; n++) acc += big[256 + n*32 + i]*big[768 + n*16 + 8 + l];
            big[512 + l*32 + i] = acc;
        }
        if (tid < ZD) {
            float acc = 0.f;
            #pragma unroll
            for (int m = 0; m < 32; m++) acc += Ac[tid*33 + m]*smu[m];
            sAmu[tid] = acc;
            if (t > 0) g_mp[(btt - 1)*ZD + tid] = acc;  // mu_pred[t] at slot t-1
        }
        __syncthreads();

        // err = y - C @ Amu
        if (tid < AD) {
            float acc = 0.f;
            #pragma unroll
            for (int m = 0; m < 32; m++) acc += sC[tid*32 + m]*sAmu[m];
            serr[tid] = a[(size_t)btt*AD + tid] - acc;
        }
        __syncthreads();

        // mu_f = Amu + Kg @ err
        if (tid < ZD) {
            float v = sAmu[tid];
            #pragma unroll
            for (int l = 0; l < 8; l++) v += big[512 + l*32 + tid]*serr[l];
            smu[tid] = v;
            g_muf[btt*ZD + tid] = v;
            if (t == Tq - 1) out_mu[btt*ZD + tid] = v;
        }
        __syncthreads();

        // sig_f = sigp - Kg @ M1 ; also prefetch A_t[b][t+1] into Anx
        #pragma unroll
        for (int q = 0; q < 4; q++) {
            int e = tid + 256*q, i = e >> 5, j = e & 31;
            float v = sigp[i*33 + j];
            #pragma unroll
            for (int l = 0; l < 8; l++) v -= big[512 + l*32 + i]*big[l*32 + j];
            sigf[e] = v;
            g_sigf[(size_t)btt*1024 + e] = v;
            if (t == Tq - 1) out_sig[(size_t)btt*1024 + e] = v;
            if (t < Tq - 1)  Anx[i*33 + j] = outA[(size_t)(btt + 1)*1024 + e];
        }
        __syncthreads();

        if (t < Tq - 1) {
            // pass6 (tiled): T1[i4][jb..jb+3] = sum_m Anx[i4][m]*sigf[m][jb..jb+3]
            {
                float x0 = 0.f, x1 = 0.f, x2 = 0.f, x3 = 0.f;
                #pragma unroll
                for (int m = 0; m < 32; m++) {
                    float av = Anx[i4*33 + m];
                    const float4 s = *(const float4*)&sigf[m*32 + jb];
                    x0 += av*s.x; x1 += av*s.y; x2 += av*s.z; x3 += av*s.w;
                }
                T1b[i4*36 + jb]     = x0;
                T1b[i4*36 + jb + 1] = x1;
                T1b[i4*36 + jb + 2] = x2;
                T1b[i4*36 + jb + 3] = x3;
                float4 r = {x0, x1, x2, x3};
                *(float4*)(g_T1s + (size_t)btt*1024 + i4*32 + jb) = r;
            }
            __syncthreads();

            // pass7 (tiled): sigp[i4][jb+s] = Q + sum_m T1[i4][m]*Anx[jb+s][m]
            {
                float a0 = (i4 == jb    ) ? 0.08f : 0.f;
                float a1 = (i4 == jb + 1) ? 0.08f : 0.f;
                float a2 = (i4 == jb + 2) ? 0.08f : 0.f;
                float a3 = (i4 == jb + 3) ? 0.08f : 0.f;
                #pragma unroll
                for (int m4 = 0; m4 < 32; m4 += 4) {
                    const float4 t4 = *(const float4*)&T1b[i4*36 + m4];
                    a0 += t4.x*Anx[(jb    )*33 + m4]     + t4.y*Anx[(jb    )*33 + m4 + 1]
                        + t4.z*Anx[(jb    )*33 + m4 + 2] + t4.w*Anx[(jb    )*33 + m4 + 3];
                    a1 += t4.x*Anx[(jb + 1)*33 + m4]     + t4.y*Anx[(jb + 1)*33 + m4 + 1]
                        + t4.z*Anx[(jb + 1)*33 + m4 + 2] + t4.w*Anx[(jb + 1)*33 + m4 + 3];
                    a2 += t4.x*Anx[(jb + 2)*33 + m4]     + t4.y*Anx[(jb + 2)*33 + m4 + 1]
                        + t4.z*Anx[(jb + 2)*33 + m4 + 2] + t4.w*Anx[(jb + 2)*33 + m4 + 3];
                    a3 += t4.x*Anx[(jb + 3)*33 + m4]     + t4.y*Anx[(jb + 3)*33 + m4 + 1]
                        + t4.z*Anx[(jb + 3)*33 + m4 + 2] + t4.w*Anx[(jb + 3)*33 + m4 + 3];
                }
                sigp[i4*33 + jb]     = a0;
                sigp[i4*33 + jb + 1] = a1;
                sigp[i4*33 + jb + 2] = a2;
                sigp[i4*33 + jb + 3] = a3;
                float4 r = {a0, a1, a2, a3};
                *(float4*)(g_sp + (size_t)btt*1024 + i4*32 + jb) = r;
            }
            __syncthreads();
        }
    }
}

// =====================================================================
// Kernel 4: batched solves X = sp^{-1} T1 (verified, unchanged).
// =====================================================================
__global__ void __launch_bounds__(256)
solve_kernel()
{
    __shared__ float big[2048];     // 32 x 64 augmented
    __shared__ float prow[64], fac[ZD];

    const int lin = blockIdx.x;     // 0 .. Bq*(Tq-1)-1
    const int b = lin / (Tq - 1), t = lin % (Tq - 1);
    const size_t bt = (size_t)b*Tq + t;
    const int tid = threadIdx.x;

    #pragma unroll
    for (int q = 0; q < 4; q++) {
        int e = tid + 256*q, i = e >> 5, j = e & 31;
        big[i*64 + j]      = g_sp[bt*1024 + e];
        big[i*64 + 32 + j] = g_T1s[bt*1024 + e];
    }
    __syncthreads();

    for (int p = 0; p < 32; p++) {
        if (tid < 64) prow[tid] = big[p*64 + tid];
        else if (tid < 96) fac[tid - 64] = big[(tid - 64)*64 + p];
        __syncthreads();
        float pinv = 1.f/prow[p];
        #pragma unroll
        for (int q = 0; q < 8; q++) {
            int e = tid + 256*q, r = e >> 6, c = e & 63;
            if (r == p) big[e] = prow[c]*pinv;
            else        big[e] -= (fac[r]*pinv)*prow[c];
        }
        __syncthreads();
    }

    #pragma unroll
    for (int q = 0; q < 4; q++) {
        int e = tid + 256*q, i = e >> 5, j = e & 31;
        g_X[bt*1024 + e] = big[i*64 + 32 + j];
    }
}

// =====================================================================
// Kernel 5: RTS backward (verified, unchanged).
// =====================================================================
__global__ void __launch_bounds__(256)
bwd_kernel(float* __restrict__ out_mu, float* __restrict__ out_sig)
{
    __shared__ __align__(16) float X[1024], D[1024], G[1024], Ssn[1024];
    __shared__ float sdm[ZD], smf[ZD], sxv[ZD], smusn[ZD];

    const int b = blockIdx.x, tid = threadIdx.x;
    const int i4 = tid >> 3, jb = (tid & 7) << 2;

    {
        const size_t bt = (size_t)b*Tq + (Tq - 1);
        ((float4*)Ssn)[tid] = ((const float4*)(g_sigf + bt*1024))[tid];
        if (tid < ZD) smusn[tid] = g_muf[bt*ZD + tid];
    }
    __syncthreads();

    for (int t = Tq - 2; t >= 0; t--) {
        const size_t bt = (size_t)b*Tq + t;
        // pass0: loads
        ((float4*)X)[tid] = ((const float4*)(g_X + bt*1024))[tid];
        {
            float4 s = ((const float4*)Ssn)[tid];
            float4 p = ((const float4*)(g_sp + bt*1024))[tid];
            float4 d = {s.x - p.x, s.y - p.y, s.z - p.z, s.w - p.w};
            ((float4*)D)[tid] = d;
        }
        if (tid < ZD) {
            sdm[tid] = smusn[tid] - g_mp[bt*ZD + tid];
            smf[tid] = g_muf[bt*ZD + tid];
        }
        __syncthreads();

        // pass A: G = D @ X ; xv = X^T dm
        {
            float g0 = 0, g1 = 0, g2 = 0, g3 = 0;
            #pragma unroll
            for (int m = 0; m < 32; m++) {
                float dv = D[i4*32 + m];
                const float4 xm = *(const float4*)&X[m*32 + jb];
                g0 += dv*xm.x; g1 += dv*xm.y; g2 += dv*xm.z; g3 += dv*xm.w;
            }
            G[i4*32 + jb] = g0; G[i4*32 + jb + 1] = g1;
            G[i4*32 + jb + 2] = g2; G[i4*32 + jb + 3] = g3;
        }
        if (tid < ZD) {
            float v = 0.f;
            #pragma unroll
            for (int k = 0; k < 32; k++) v += X[k*32 + tid]*sdm[k];
            sxv[tid] = v;
        }
        __syncthreads();

        // pass B: sig_s = sf + X^T G ; mu_s = mf + xv
        {
            float4 acc = ((const float4*)(g_sigf + bt*1024))[tid];
            #pragma unroll
            for (int k = 0; k < 32; k++) {
                float xk = X[k*32 + i4];
                const float4 g4 = *(const float4*)&G[k*32 + jb];
                acc.x += xk*g4.x; acc.y += xk*g4.y; acc.z += xk*g4.z; acc.w += xk*g4.w;
            }
            ((float4*)(out_sig + bt*1024))[tid] = acc;
            ((float4*)Ssn)[tid] = acc;
        }
        if (tid < ZD) {
            float v = smf[tid] + sxv[tid];
            out_mu[bt*ZD + tid] = v;
            smusn[tid] = v;
        }
        __syncthreads();
    }
}

// =====================================================================
extern "C" void kernel_launch(void* const* d_in, const int* in_sizes, int n_in,
                              void* d_out, int out_size)
{
    const float* a       = (const float*)d_in[0];
    const float* a1      = (const float*)d_in[1];
    const float* W_ih    = (const float*)d_in[2];
    const float* W_hh    = (const float*)d_in[3];
    const float* b_ih    = (const float*)d_in[4];
    const float* b_hh    = (const float*)d_in[5];
    const float* W_alpha = (const float*)d_in[6];
    const float* b_alpha = (const float*)d_in[7];
    const float* Ag      = (const float*)d_in[8];
    const float* Cg      = (const float*)d_in[9];

    float* out    = (float*)d_out;
    float* out_mu = out;                              // [B,T,32]
    float* out_sg = out_mu + (size_t)BT*ZD;           // [B,T,32,32]
    float* out_A  = out_sg + (size_t)BT*ZD*ZD;        // [B,T,32,32]
    float* out_C  = out_A  + (size_t)BT*ZD*ZD;        // [B,T,8,32]

    lstm_kernel<<<Bq, 256>>>(a, a1, W_ih, W_hh, b_ih, b_hh, W_alpha, b_alpha);
    mix_kernel<<<BT/128, 256>>>(Ag, Cg, out_A, out_C);
    fwd_kernel<<<Bq, 256>>>(a, out_mu, out_sg, out_A, out_C);
    solve_kernel<<<Bq*(Tq - 1), 256>>>();
    bwd_kernel<<<Bq, 256>>>(out_mu, out_sg);
}

// round 9
// speedup vs baseline: 1.4686x; 1.4686x over previous
#include <cuda_runtime.h>

// ---------------- problem constants ----------------
#define Bq   256
#define Tq   128
#define AD   8
#define ZD   32
#define KM   16
#define HIDq 50
#define BT   (Bq*Tq)

// ---------------- device scratch ----------------
__device__ float g_w[BT*KM];
__device__ float g_sigf[(size_t)BT*1024];   // Sigma_f[t]
__device__ float g_T1s[(size_t)BT*1024];    // T1 = A_{t+1} Sigma_f[t]   (slot t, t<=T-2)
__device__ float g_sp[(size_t)BT*1024];     // Sigma_pred[t+1]           (slot t, t<=T-2)
__device__ float g_X[(size_t)BT*1024];      // X = sp^{-1} T1 (= J^T)    (slot t, t<=T-2)
__device__ float g_muf[BT*ZD];              // mu_f[t]
__device__ float g_mp[BT*ZD];               // mu_pred[t+1]              (slot t, t<=T-2)

// =====================================================================
// Kernel 1: LSTM over T + softmax mixture weights (round-8 verified).
// =====================================================================
__global__ void __launch_bounds__(256)
lstm_kernel(const float* __restrict__ a,  const float* __restrict__ a1,
            const float* __restrict__ W_ih, const float* __restrict__ W_hh,
            const float* __restrict__ b_ih, const float* __restrict__ b_hh,
            const float* __restrict__ W_alpha, const float* __restrict__ b_alpha)
{
    __shared__ float sWhh[HIDq*200];     // transposed: [j][g]
    __shared__ float sWa[KM*HIDq];
    __shared__ float sh[HIDq], sc[HIDq], sx[AD], sg[200];

    const int b = blockIdx.x, tid = threadIdx.x;

    float wi[AD]; float bg = 0.f;
    if (tid < 200) {
        #pragma unroll
        for (int j = 0; j < AD; j++) wi[j] = W_ih[tid*AD + j];
        bg = b_ih[tid] + b_hh[tid];
    }
    for (int i = tid; i < 200*HIDq; i += 256) {
        int g = i / HIDq, j = i % HIDq;
        sWhh[j*200 + g] = W_hh[i];
    }
    for (int i = tid; i < KM*HIDq; i += 256) sWa[i] = W_alpha[i];
    if (tid < HIDq) { sh[tid] = 0.f; sc[tid] = 0.f; }
    __syncthreads();

    for (int t = 0; t < Tq; t++) {
        if (tid < AD) sx[tid] = (t == 0) ? a1[tid] : a[(b*Tq + (t-1))*AD + tid];
        __syncthreads();                 // B1
        if (tid < 200) {
            float a0 = bg, a1_ = 0.f, a2 = 0.f, a3 = 0.f;
            #pragma unroll
            for (int j = 0; j < AD; j++) a0 += sx[j]*wi[j];
            #pragma unroll
            for (int j = 0; j < 48; j += 4) {
                a0  += sh[j  ]*sWhh[(j  )*200 + tid];
                a1_ += sh[j+1]*sWhh[(j+1)*200 + tid];
                a2  += sh[j+2]*sWhh[(j+2)*200 + tid];
                a3  += sh[j+3]*sWhh[(j+3)*200 + tid];
            }
            a0  += sh[48]*sWhh[48*200 + tid];
            a1_ += sh[49]*sWhh[49*200 + tid];
            sg[tid] = (a0 + a1_) + (a2 + a3);
        }
        __syncthreads();                 // B2
        if (tid < HIDq) {
            float ig = 1.f/(1.f + __expf(-sg[tid]));
            float fg = 1.f/(1.f + __expf(-sg[HIDq + tid]));
            float gg = tanhf(sg[2*HIDq + tid]);
            float og = 1.f/(1.f + __expf(-sg[3*HIDq + tid]));
            float c  = fg*sc[tid] + ig*gg;
            sc[tid] = c;
            sh[tid] = og*tanhf(c);
        }
        __syncthreads();                 // B3
        if (tid < 32) {
            float logit = -1e30f;
            if (tid < KM) {
                logit = b_alpha[tid];
                #pragma unroll
                for (int j = 0; j < HIDq; j++) logit += sh[j]*sWa[tid*HIDq + j];
            }
            float m = logit;
            #pragma unroll
            for (int d = 8; d; d >>= 1)
                m = fmaxf(m, __shfl_xor_sync(0xffffffffu, m, d, 16));
            float e = __expf(logit - m);
            float s = e;
            #pragma unroll
            for (int d = 8; d; d >>= 1)
                s += __shfl_xor_sync(0xffffffffu, s, d, 16);
            if (tid < KM) g_w[(b*Tq + t)*KM + tid] = e/s;
        }
    }
}

// =====================================================================
// Kernel 2: A_t/C_t mixing (verified, unchanged).
// =====================================================================
__global__ void __launch_bounds__(256)
mix_kernel(const float* __restrict__ Ag, const float* __restrict__ Cg,
           float* __restrict__ outA, float* __restrict__ outC)
{
    __shared__ float sw[128*KM];
    const int tid = threadIdx.x;
    const int r0  = blockIdx.x * 128;
    for (int i = tid; i < 128*KM; i += 256) sw[i] = g_w[r0*KM + i];
    __syncthreads();

    for (int c = tid; c < 1280; c += 256) {
        float av[KM];
        if (c < 1024) {
            #pragma unroll
            for (int k = 0; k < KM; k++) av[k] = Ag[k*1024 + c];
            for (int r = 0; r < 128; r++) {
                float acc = 0.f;
                #pragma unroll
                for (int k = 0; k < KM; k++) acc += sw[r*KM + k]*av[k];
                outA[(size_t)(r0 + r)*1024 + c] = acc;
            }
        } else {
            const int cc = c - 1024;
            #pragma unroll
            for (int k = 0; k < KM; k++) av[k] = Cg[k*256 + cc];
            for (int r = 0; r < 128; r++) {
                float acc = 0.f;
                #pragma unroll
                for (int k = 0; k < KM; k++) acc += sw[r*KM + k]*av[k];
                outC[(r0 + r)*256 + cc] = acc;
            }
        }
    }
}

// =====================================================================
// Kernel 3: Kalman forward filter (round-8 verified, unchanged).
// Kg comes from Pt (rows of sigp) — load-bearing for stability.
// =====================================================================
__global__ void __launch_bounds__(256)
fwd_kernel(const float* __restrict__ a,
           float* __restrict__ out_mu, float* __restrict__ out_sig,
           const float* __restrict__ outA, const float* __restrict__ outC)
{
    __shared__ float sAbuf[2*1056];                 // ping-pong A (stride 33)
    __shared__ float sC[256];                       // C_t [8][32]
    __shared__ float sigp[1056];                    // sig_pred (stride 33)
    __shared__ __align__(16) float sigf[1024];      // sig_filt (stride 32)
    __shared__ float big[1024];                     // M1 | Pt | KgT | aug8
    __shared__ __align__(16) float T1b[32*36];      // T1 (stride 36)
    __shared__ float sAmu[ZD], serr[AD], smu[ZD];

    const int b = blockIdx.x, tid = threadIdx.x;
    const int i4 = tid >> 3;                // tiled-output row (0..31)
    const int jb = (tid & 7) << 2;          // tiled-output col block (x4)

    // ---- init: sig_pred = 20*I, mu = 0, load A_t[b][0] ----
    for (int e = tid; e < 1024; e += 256) {
        int i = e >> 5, j = e & 31;
        sigp[i*33 + j] = (i == j) ? 20.f : 0.f;
        sAbuf[i*33 + j] = outA[(size_t)(b*Tq)*1024 + e];
    }
    if (tid < ZD) smu[tid] = 0.f;
    __syncthreads();

    for (int t = 0; t < Tq; t++) {
        float* Ac  = sAbuf + (t & 1)*1056;
        float* Anx = sAbuf + ((t + 1) & 1)*1056;
        const int btt = b*Tq + t;

        sC[tid] = outC[(size_t)btt*256 + tid];
        __syncthreads();

        // M1 = C @ sigp (8x32) ; Pt[l][i] = (sigp C^T)[i][l] (store transposed)
        {
            int l = tid >> 5, j = tid & 31;
            float acc = 0.f;
            #pragma unroll
            for (int m = 0; m < 32; m++) acc += sC[l*32 + m]*sigp[m*33 + j];
            big[l*32 + j] = acc;
            int i = tid & 31, l2 = tid >> 5;
            float acc2 = 0.f;
            #pragma unroll
            for (int m = 0; m < 32; m++) acc2 += sigp[i*33 + m]*sC[l2*32 + m];
            big[256 + l2*32 + i] = acc2;
        }
        __syncthreads();

        // S = M1 @ C^T + R  ->  augmented [S | I] at big+768 (8x16)
        if (tid < 64) {
            int l = tid >> 3, n = tid & 7;
            float acc = 0.f;
            #pragma unroll
            for (int m = 0; m < 32; m++) acc += big[l*32 + m]*sC[n*32 + m];
            big[768 + l*16 + n]     = acc + ((l == n) ? 0.03f : 0.f);
            big[768 + l*16 + 8 + n] = (l == n) ? 1.f : 0.f;
        }
        __syncthreads();

        // invert 8x8 SPD (Gauss-Jordan, warp 0 only, verified)
        if (tid < 32) {
            int r = tid >> 2, c0 = (tid & 3)*4;
            #pragma unroll
            for (int p = 0; p < 8; p++) {
                float fc  = big[768 + r*16 + p];
                float p0 = big[768 + p*16 + c0];
                float p1 = big[768 + p*16 + c0 + 1];
                float p2 = big[768 + p*16 + c0 + 2];
                float p3 = big[768 + p*16 + c0 + 3];
                float pd = big[768 + p*16 + p];
                __syncwarp();
                float pinv = 1.f/pd;
                if (r == p) {
                    big[768 + r*16 + c0]     = p0*pinv;
                    big[768 + r*16 + c0 + 1] = p1*pinv;
                    big[768 + r*16 + c0 + 2] = p2*pinv;
                    big[768 + r*16 + c0 + 3] = p3*pinv;
                } else {
                    float f = fc*pinv;
                    big[768 + r*16 + c0]     -= f*p0;
                    big[768 + r*16 + c0 + 1] -= f*p1;
                    big[768 + r*16 + c0 + 2] -= f*p2;
                    big[768 + r*16 + c0 + 3] -= f*p3;
                }
                __syncwarp();
            }
        }
        __syncthreads();

        // Kg^T[l][i] = sum_n Pt[n][i] * Sinv[n][l]   (at 512 + l*32 + i)
        {
            int l = tid >> 5, i = tid & 31;
            float acc = 0.f;
            #pragma unroll
            for (int n = 0; n < 8; n++) acc += big[256 + n*32 + i]*big[768 + n*16 + 8 + l];
            big[512 + l*32 + i] = acc;
        }
        if (tid < ZD) {
            float acc = 0.f;
            #pragma unroll
            for (int m = 0; m < 32; m++) acc += Ac[tid*33 + m]*smu[m];
            sAmu[tid] = acc;
            if (t > 0) g_mp[(btt - 1)*ZD + tid] = acc;  // mu_pred[t] at slot t-1
        }
        __syncthreads();

        // err = y - C @ Amu
        if (tid < AD) {
            float acc = 0.f;
            #pragma unroll
            for (int m = 0; m < 32; m++) acc += sC[tid*32 + m]*sAmu[m];
            serr[tid] = a[(size_t)btt*AD + tid] - acc;
        }
        __syncthreads();

        // mu_f = Amu + Kg @ err
        if (tid < ZD) {
            float v = sAmu[tid];
            #pragma unroll
            for (int l = 0; l < 8; l++) v += big[512 + l*32 + tid]*serr[l];
            smu[tid] = v;
            g_muf[btt*ZD + tid] = v;
            if (t == Tq - 1) out_mu[btt*ZD + tid] = v;
        }
        __syncthreads();

        // sig_f = sigp - Kg @ M1 ; also prefetch A_t[b][t+1] into Anx
        #pragma unroll
        for (int q = 0; q < 4; q++) {
            int e = tid + 256*q, i = e >> 5, j = e & 31;
            float v = sigp[i*33 + j];
            #pragma unroll
            for (int l = 0; l < 8; l++) v -= big[512 + l*32 + i]*big[l*32 + j];
            sigf[e] = v;
            g_sigf[(size_t)btt*1024 + e] = v;
            if (t == Tq - 1) out_sig[(size_t)btt*1024 + e] = v;
            if (t < Tq - 1)  Anx[i*33 + j] = outA[(size_t)(btt + 1)*1024 + e];
        }
        __syncthreads();

        if (t < Tq - 1) {
            // pass6 (tiled): T1[i4][jb..jb+3] = sum_m Anx[i4][m]*sigf[m][jb..jb+3]
            {
                float x0 = 0.f, x1 = 0.f, x2 = 0.f, x3 = 0.f;
                #pragma unroll
                for (int m = 0; m < 32; m++) {
                    float av = Anx[i4*33 + m];
                    const float4 s = *(const float4*)&sigf[m*32 + jb];
                    x0 += av*s.x; x1 += av*s.y; x2 += av*s.z; x3 += av*s.w;
                }
                T1b[i4*36 + jb]     = x0;
                T1b[i4*36 + jb + 1] = x1;
                T1b[i4*36 + jb + 2] = x2;
                T1b[i4*36 + jb + 3] = x3;
                float4 r = {x0, x1, x2, x3};
                *(float4*)(g_T1s + (size_t)btt*1024 + i4*32 + jb) = r;
            }
            __syncthreads();

            // pass7 (tiled): sigp[i4][jb+s] = Q + sum_m T1[i4][m]*Anx[jb+s][m]
            {
                float a0 = (i4 == jb    ) ? 0.08f : 0.f;
                float a1 = (i4 == jb + 1) ? 0.08f : 0.f;
                float a2 = (i4 == jb + 2) ? 0.08f : 0.f;
                float a3 = (i4 == jb + 3) ? 0.08f : 0.f;
                #pragma unroll
                for (int m4 = 0; m4 < 32; m4 += 4) {
                    const float4 t4 = *(const float4*)&T1b[i4*36 + m4];
                    a0 += t4.x*Anx[(jb    )*33 + m4]     + t4.y*Anx[(jb    )*33 + m4 + 1]
                        + t4.z*Anx[(jb    )*33 + m4 + 2] + t4.w*Anx[(jb    )*33 + m4 + 3];
                    a1 += t4.x*Anx[(jb + 1)*33 + m4]     + t4.y*Anx[(jb + 1)*33 + m4 + 1]
                        + t4.z*Anx[(jb + 1)*33 + m4 + 2] + t4.w*Anx[(jb + 1)*33 + m4 + 3];
                    a2 += t4.x*Anx[(jb + 2)*33 + m4]     + t4.y*Anx[(jb + 2)*33 + m4 + 1]
                        + t4.z*Anx[(jb + 2)*33 + m4 + 2] + t4.w*Anx[(jb + 2)*33 + m4 + 3];
                    a3 += t4.x*Anx[(jb + 3)*33 + m4]     + t4.y*Anx[(jb + 3)*33 + m4 + 1]
                        + t4.z*Anx[(jb + 3)*33 + m4 + 2] + t4.w*Anx[(jb + 3)*33 + m4 + 3];
                }
                sigp[i4*33 + jb]     = a0;
                sigp[i4*33 + jb + 1] = a1;
                sigp[i4*33 + jb + 2] = a2;
                sigp[i4*33 + jb + 3] = a3;
                float4 r = {a0, a1, a2, a3};
                *(float4*)(g_sp + (size_t)btt*1024 + i4*32 + jb) = r;
            }
            __syncthreads();
        }
    }
}

// =====================================================================
// Kernel 4: batched solves X = sp^{-1} T1 (one CTA per (b,t), t<=T-2).
// REGISTER-RESIDENT Gauss-Jordan on the 32x64 augmented [sp | T1]:
// thread (c = tid>>2, q = tid&3) owns rows q*8..q*8+7 of column c in
// registers. Pivot row p fetched pre-update via width-4 shuffle from
// lane q = p>>3; pivot column double-buffered in shared. 1 barrier/pivot.
// Dead columns (c <= p, left block) skipped — same live-set arithmetic
// as the verified shared-memory version.
// =====================================================================
__global__ void __launch_bounds__(256)
solve_kernel()
{
    const int lin = blockIdx.x;             // 0 .. Bq*(Tq-1)-1
    const int b = lin / (Tq - 1), t = lin % (Tq - 1);
    const size_t bt = (size_t)b*Tq + t;
    const int tid = threadIdx.x;
    const int c = tid >> 2, q = tid & 3;

    __shared__ float sfac[2][32];
    __shared__ float spinv[2];

    float reg[8];
    {
        const float* M0 = (c < 32) ? (g_sp + bt*1024 + c) : (g_T1s + bt*1024 + (c - 32));
        #pragma unroll
        for (int i = 0; i < 8; i++) reg[i] = M0[(q*8 + i)*32];
    }
    // pivot-0 prep: column 0 snapshot + reciprocal
    if (c == 0) {
        #pragma unroll
        for (int i = 0; i < 8; i++) sfac[0][q*8 + i] = reg[i];
        if (q == 0) spinv[0] = 1.f/reg[0];
    }
    __syncthreads();

    #pragma unroll
    for (int p = 0; p < 32; p++) {
        const int pb = p & 1;
        const float piv = spinv[pb];
        float fac[8];
        #pragma unroll
        for (int i = 0; i < 8; i++) fac[i] = sfac[pb][q*8 + i];
        // row-p element of my column (pre-update), from the lane with q = p>>3
        float m_pc = __shfl_sync(0xffffffffu, reg[p & 7], p >> 3, 4);
        float mn = m_pc * piv;
        if (c > p) {
            #pragma unroll
            for (int i = 0; i < 8; i++) {
                int r = q*8 + i;
                reg[i] = (r == p) ? mn : (reg[i] - fac[i]*mn);
            }
            if (p < 31 && c == p + 1) {
                #pragma unroll
                for (int i = 0; i < 8; i++) sfac[pb ^ 1][q*8 + i] = reg[i];
                if (q == ((p + 1) >> 3)) spinv[pb ^ 1] = 1.f/reg[(p + 1) & 7];
            }
        }
        __syncthreads();
    }

    if (c >= 32) {
        float* Xo = g_X + bt*1024 + (c - 32);
        #pragma unroll
        for (int i = 0; i < 8; i++) Xo[(q*8 + i)*32] = reg[i];
    }
}

// =====================================================================
// Kernel 5: RTS backward (verified, unchanged).
// =====================================================================
__global__ void __launch_bounds__(256)
bwd_kernel(float* __restrict__ out_mu, float* __restrict__ out_sig)
{
    __shared__ __align__(16) float X[1024], D[1024], G[1024], Ssn[1024];
    __shared__ float sdm[ZD], smf[ZD], sxv[ZD], smusn[ZD];

    const int b = blockIdx.x, tid = threadIdx.x;
    const int i4 = tid >> 3, jb = (tid & 7) << 2;

    {
        const size_t bt = (size_t)b*Tq + (Tq - 1);
        ((float4*)Ssn)[tid] = ((const float4*)(g_sigf + bt*1024))[tid];
        if (tid < ZD) smusn[tid] = g_muf[bt*ZD + tid];
    }
    __syncthreads();

    for (int t = Tq - 2; t >= 0; t--) {
        const size_t bt = (size_t)b*Tq + t;
        // pass0: loads
        ((float4*)X)[tid] = ((const float4*)(g_X + bt*1024))[tid];
        {
            float4 s = ((const float4*)Ssn)[tid];
            float4 p = ((const float4*)(g_sp + bt*1024))[tid];
            float4 d = {s.x - p.x, s.y - p.y, s.z - p.z, s.w - p.w};
            ((float4*)D)[tid] = d;
        }
        if (tid < ZD) {
            sdm[tid] = smusn[tid] - g_mp[bt*ZD + tid];
            smf[tid] = g_muf[bt*ZD + tid];
        }
        __syncthreads();

        // pass A: G = D @ X ; xv = X^T dm
        {
            float g0 = 0, g1 = 0, g2 = 0, g3 = 0;
            #pragma unroll
            for (int m = 0; m < 32; m++) {
                float dv = D[i4*32 + m];
                const float4 xm = *(const float4*)&X[m*32 + jb];
                g0 += dv*xm.x; g1 += dv*xm.y; g2 += dv*xm.z; g3 += dv*xm.w;
            }
            G[i4*32 + jb] = g0; G[i4*32 + jb + 1] = g1;
            G[i4*32 + jb + 2] = g2; G[i4*32 + jb + 3] = g3;
        }
        if (tid < ZD) {
            float v = 0.f;
            #pragma unroll
            for (int k = 0; k < 32; k++) v += X[k*32 + tid]*sdm[k];
            sxv[tid] = v;
        }
        __syncthreads();

        // pass B: sig_s = sf + X^T G ; mu_s = mf + xv
        {
            float4 acc = ((const float4*)(g_sigf + bt*1024))[tid];
            #pragma unroll
            for (int k = 0; k < 32; k++) {
                float xk = X[k*32 + i4];
                const float4 g4 = *(const float4*)&G[k*32 + jb];
                acc.x += xk*g4.x; acc.y += xk*g4.y; acc.z += xk*g4.z; acc.w += xk*g4.w;
            }
            ((float4*)(out_sig + bt*1024))[tid] = acc;
            ((float4*)Ssn)[tid] = acc;
        }
        if (tid < ZD) {
            float v = smf[tid] + sxv[tid];
            out_mu[bt*ZD + tid] = v;
            smusn[tid] = v;
        }
        __syncthreads();
    }
}

// =====================================================================
extern "C" void kernel_launch(void* const* d_in, const int* in_sizes, int n_in,
                              void* d_out, int out_size)
{
    const float* a       = (const float*)d_in[0];
    const float* a1      = (const float*)d_in[1];
    const float* W_ih    = (const float*)d_in[2];
    const float* W_hh    = (const float*)d_in[3];
    const float* b_ih    = (const float*)d_in[4];
    const float* b_hh    = (const float*)d_in[5];
    const float* W_alpha = (const float*)d_in[6];
    const float* b_alpha = (const float*)d_in[7];
    const float* Ag      = (const float*)d_in[8];
    const float* Cg      = (const float*)d_in[9];

    float* out    = (float*)d_out;
    float* out_mu = out;                              // [B,T,32]
    float* out_sg = out_mu + (size_t)BT*ZD;           // [B,T,32,32]
    float* out_A  = out_sg + (size_t)BT*ZD*ZD;        // [B,T,32,32]
    float* out_C  = out_A  + (size_t)BT*ZD*ZD;        // [B,T,8,32]

    lstm_kernel<<<Bq, 256>>>(a, a1, W_ih, W_hh, b_ih, b_hh, W_alpha, b_alpha);
    mix_kernel<<<BT/128, 256>>>(Ag, Cg, out_A, out_C);
    fwd_kernel<<<Bq, 256>>>(a, out_mu, out_sg, out_A, out_C);
    solve_kernel<<<Bq*(Tq - 1), 256>>>();
    bwd_kernel<<<Bq, 256>>>(out_mu, out_sg);
}

// round 10
// speedup vs baseline: 1.5201x; 1.0351x over previous
#include <cuda_runtime.h>

// ---------------- problem constants ----------------
#define Bq   256
#define Tq   128
#define AD   8
#define ZD   32
#define KM   16
#define HIDq 50
#define BT   (Bq*Tq)

// ---------------- device scratch ----------------
__device__ float g_w[BT*KM];
__device__ float g_sigf[(size_t)BT*1024];   // Sigma_f[t]
__device__ float g_T1s[(size_t)BT*1024];    // T1 = A_{t+1} Sigma_f[t]   (slot t, t<=T-2)
__device__ float g_sp[(size_t)BT*1024];     // Sigma_pred[t+1]           (slot t, t<=T-2)
__device__ float g_X[(size_t)BT*1024];      // X = sp^{-1} T1 (= J^T)    (slot t, t<=T-2)
__device__ float g_muf[BT*ZD];              // mu_f[t]
__device__ float g_mp[BT*ZD];               // mu_pred[t+1]              (slot t, t<=T-2)

// =====================================================================
// Kernel 1: LSTM over T + softmax mixture weights (verified, unchanged).
// =====================================================================
__global__ void __launch_bounds__(256)
lstm_kernel(const float* __restrict__ a,  const float* __restrict__ a1,
            const float* __restrict__ W_ih, const float* __restrict__ W_hh,
            const float* __restrict__ b_ih, const float* __restrict__ b_hh,
            const float* __restrict__ W_alpha, const float* __restrict__ b_alpha)
{
    __shared__ float sWhh[HIDq*200];     // transposed: [j][g]
    __shared__ float sWa[KM*HIDq];
    __shared__ float sh[HIDq], sc[HIDq], sx[AD], sg[200];

    const int b = blockIdx.x, tid = threadIdx.x;

    float wi[AD]; float bg = 0.f;
    if (tid < 200) {
        #pragma unroll
        for (int j = 0; j < AD; j++) wi[j] = W_ih[tid*AD + j];
        bg = b_ih[tid] + b_hh[tid];
    }
    for (int i = tid; i < 200*HIDq; i += 256) {
        int g = i / HIDq, j = i % HIDq;
        sWhh[j*200 + g] = W_hh[i];
    }
    for (int i = tid; i < KM*HIDq; i += 256) sWa[i] = W_alpha[i];
    if (tid < HIDq) { sh[tid] = 0.f; sc[tid] = 0.f; }
    __syncthreads();

    for (int t = 0; t < Tq; t++) {
        if (tid < AD) sx[tid] = (t == 0) ? a1[tid] : a[(b*Tq + (t-1))*AD + tid];
        __syncthreads();                 // B1
        if (tid < 200) {
            float a0 = bg, a1_ = 0.f, a2 = 0.f, a3 = 0.f;
            #pragma unroll
            for (int j = 0; j < AD; j++) a0 += sx[j]*wi[j];
            #pragma unroll
            for (int j = 0; j < 48; j += 4) {
                a0  += sh[j  ]*sWhh[(j  )*200 + tid];
                a1_ += sh[j+1]*sWhh[(j+1)*200 + tid];
                a2  += sh[j+2]*sWhh[(j+2)*200 + tid];
                a3  += sh[j+3]*sWhh[(j+3)*200 + tid];
            }
            a0  += sh[48]*sWhh[48*200 + tid];
            a1_ += sh[49]*sWhh[49*200 + tid];
            sg[tid] = (a0 + a1_) + (a2 + a3);
        }
        __syncthreads();                 // B2
        if (tid < HIDq) {
            float ig = 1.f/(1.f + __expf(-sg[tid]));
            float fg = 1.f/(1.f + __expf(-sg[HIDq + tid]));
            float gg = tanhf(sg[2*HIDq + tid]);
            float og = 1.f/(1.f + __expf(-sg[3*HIDq + tid]));
            float c  = fg*sc[tid] + ig*gg;
            sc[tid] = c;
            sh[tid] = og*tanhf(c);
        }
        __syncthreads();                 // B3
        if (tid < 32) {
            float logit = -1e30f;
            if (tid < KM) {
                logit = b_alpha[tid];
                #pragma unroll
                for (int j = 0; j < HIDq; j++) logit += sh[j]*sWa[tid*HIDq + j];
            }
            float m = logit;
            #pragma unroll
            for (int d = 8; d; d >>= 1)
                m = fmaxf(m, __shfl_xor_sync(0xffffffffu, m, d, 16));
            float e = __expf(logit - m);
            float s = e;
            #pragma unroll
            for (int d = 8; d; d >>= 1)
                s += __shfl_xor_sync(0xffffffffu, s, d, 16);
            if (tid < KM) g_w[(b*Tq + t)*KM + tid] = e/s;
        }
    }
}

// =====================================================================
// Kernel 2: A_t/C_t mixing (verified, unchanged).
// =====================================================================
__global__ void __launch_bounds__(256)
mix_kernel(const float* __restrict__ Ag, const float* __restrict__ Cg,
           float* __restrict__ outA, float* __restrict__ outC)
{
    __shared__ float sw[128*KM];
    const int tid = threadIdx.x;
    const int r0  = blockIdx.x * 128;
    for (int i = tid; i < 128*KM; i += 256) sw[i] = g_w[r0*KM + i];
    __syncthreads();

    for (int c = tid; c < 1280; c += 256) {
        float av[KM];
        if (c < 1024) {
            #pragma unroll
            for (int k = 0; k < KM; k++) av[k] = Ag[k*1024 + c];
            for (int r = 0; r < 128; r++) {
                float acc = 0.f;
                #pragma unroll
                for (int k = 0; k < KM; k++) acc += sw[r*KM + k]*av[k];
                outA[(size_t)(r0 + r)*1024 + c] = acc;
            }
        } else {
            const int cc = c - 1024;
            #pragma unroll
            for (int k = 0; k < KM; k++) av[k] = Cg[k*256 + cc];
            for (int r = 0; r < 128; r++) {
                float acc = 0.f;
                #pragma unroll
                for (int k = 0; k < KM; k++) acc += sw[r*KM + k]*av[k];
                outC[(r0 + r)*256 + cc] = acc;
            }
        }
    }
}

// =====================================================================
// Kernel 3: Kalman forward filter — round-9 math, rescheduled 10->8
// barrier phases:
//   B1: sC load + Amu (tid<32) + g_mp store
//   B2: M1/Pt    B3: S + err    B4: inv    B5: KgT
//   B6: sigf + prefetch + mu_f  B7: T1     B8: sigp
// Kg comes from Pt (rows of sigp) — load-bearing for stability.
// =====================================================================
__global__ void __launch_bounds__(256)
fwd_kernel(const float* __restrict__ a,
           float* __restrict__ out_mu, float* __restrict__ out_sig,
           const float* __restrict__ outA, const float* __restrict__ outC)
{
    __shared__ float sAbuf[2*1056];                 // ping-pong A (stride 33)
    __shared__ float sC[256];                       // C_t [8][32]
    __shared__ float sigp[1056];                    // sig_pred (stride 33)
    __shared__ __align__(16) float sigf[1024];      // sig_filt (stride 32)
    __shared__ float big[1024];                     // M1 | Pt | KgT | aug8
    __shared__ __align__(16) float T1b[32*36];      // T1 (stride 36)
    __shared__ float sAmu[ZD], serr[AD], smu[ZD];

    const int b = blockIdx.x, tid = threadIdx.x;
    const int i4 = tid >> 3;                // tiled-output row (0..31)
    const int jb = (tid & 7) << 2;          // tiled-output col block (x4)

    // ---- init: sig_pred = 20*I, mu = 0, load A_t[b][0] ----
    for (int e = tid; e < 1024; e += 256) {
        int i = e >> 5, j = e & 31;
        sigp[i*33 + j] = (i == j) ? 20.f : 0.f;
        sAbuf[i*33 + j] = outA[(size_t)(b*Tq)*1024 + e];
    }
    if (tid < ZD) smu[tid] = 0.f;
    __syncthreads();

    for (int t = 0; t < Tq; t++) {
        float* Ac  = sAbuf + (t & 1)*1056;
        float* Anx = sAbuf + ((t + 1) & 1)*1056;
        const int btt = b*Tq + t;

        // B1 phase: sC load + Amu = Ac @ mu (reads stable Ac, smu)
        sC[tid] = outC[(size_t)btt*256 + tid];
        if (tid < ZD) {
            float acc = 0.f;
            #pragma unroll
            for (int m = 0; m < 32; m++) acc += Ac[tid*33 + m]*smu[m];
            sAmu[tid] = acc;
            if (t > 0) g_mp[(btt - 1)*ZD + tid] = acc;  // mu_pred[t] at slot t-1
        }
        __syncthreads();   // B1

        // B2 phase: M1 = C @ sigp ; Pt[l][i] = (sigp C^T)[i][l]
        {
            int l = tid >> 5, j = tid & 31;
            float acc = 0.f;
            #pragma unroll
            for (int m = 0; m < 32; m++) acc += sC[l*32 + m]*sigp[m*33 + j];
            big[l*32 + j] = acc;
            int i = tid & 31, l2 = tid >> 5;
            float acc2 = 0.f;
            #pragma unroll
            for (int m = 0; m < 32; m++) acc2 += sigp[i*33 + m]*sC[l2*32 + m];
            big[256 + l2*32 + i] = acc2;
        }
        __syncthreads();   // B2

        // B3 phase: S = M1 C^T + R -> [S|I] (tid<64) | err (tid 64..71)
        if (tid < 64) {
            int l = tid >> 3, n = tid & 7;
            float acc = 0.f;
            #pragma unroll
            for (int m = 0; m < 32; m++) acc += big[l*32 + m]*sC[n*32 + m];
            big[768 + l*16 + n]     = acc + ((l == n) ? 0.03f : 0.f);
            big[768 + l*16 + 8 + n] = (l == n) ? 1.f : 0.f;
        } else if (tid < 72) {
            int l = tid - 64;
            float acc = 0.f;
            #pragma unroll
            for (int m = 0; m < 32; m++) acc += sC[l*32 + m]*sAmu[m];
            serr[l] = a[(size_t)btt*AD + l] - acc;
        }
        __syncthreads();   // B3

        // B4 phase: invert 8x8 SPD (warp 0, Gauss-Jordan, verified)
        if (tid < 32) {
            int r = tid >> 2, c0 = (tid & 3)*4;
            #pragma unroll
            for (int p = 0; p < 8; p++) {
                float fc  = big[768 + r*16 + p];
                float p0 = big[768 + p*16 + c0];
                float p1 = big[768 + p*16 + c0 + 1];
                float p2 = big[768 + p*16 + c0 + 2];
                float p3 = big[768 + p*16 + c0 + 3];
                float pd = big[768 + p*16 + p];
                __syncwarp();
                float pinv = 1.f/pd;
                if (r == p) {
                    big[768 + r*16 + c0]     = p0*pinv;
                    big[768 + r*16 + c0 + 1] = p1*pinv;
                    big[768 + r*16 + c0 + 2] = p2*pinv;
                    big[768 + r*16 + c0 + 3] = p3*pinv;
                } else {
                    float f = fc*pinv;
                    big[768 + r*16 + c0]     -= f*p0;
                    big[768 + r*16 + c0 + 1] -= f*p1;
                    big[768 + r*16 + c0 + 2] -= f*p2;
                    big[768 + r*16 + c0 + 3] -= f*p3;
                }
                __syncwarp();
            }
        }
        __syncthreads();   // B4

        // B5 phase: Kg^T[l][i] = sum_n Pt[n][i] * Sinv[n][l]
        {
            int l = tid >> 5, i = tid & 31;
            float acc = 0.f;
            #pragma unroll
            for (int n = 0; n < 8; n++) acc += big[256 + n*32 + i]*big[768 + n*16 + 8 + l];
            big[512 + l*32 + i] = acc;
        }
        __syncthreads();   // B5

        // B6 phase: sig_f = sigp - Kg @ M1 (all) + prefetch A_{t+1}
        //           + mu_f = Amu + Kg @ err (tid<32)
        #pragma unroll
        for (int q = 0; q < 4; q++) {
            int e = tid + 256*q, i = e >> 5, j = e & 31;
            float v = sigp[i*33 + j];
            #pragma unroll
            for (int l = 0; l < 8; l++) v -= big[512 + l*32 + i]*big[l*32 + j];
            sigf[e] = v;
            g_sigf[(size_t)btt*1024 + e] = v;
            if (t == Tq - 1) out_sig[(size_t)btt*1024 + e] = v;
            if (t < Tq - 1)  Anx[i*33 + j] = outA[(size_t)(btt + 1)*1024 + e];
        }
        if (tid < ZD) {
            float v = sAmu[tid];
            #pragma unroll
            for (int l = 0; l < 8; l++) v += big[512 + l*32 + tid]*serr[l];
            smu[tid] = v;
            g_muf[btt*ZD + tid] = v;
            if (t == Tq - 1) out_mu[btt*ZD + tid] = v;
        }
        __syncthreads();   // B6

        if (t < Tq - 1) {
            // B7 phase (tiled): T1[i4][jb..jb+3] = sum_m Anx[i4][m]*sigf[m][jb..+3]
            {
                float x0 = 0.f, x1 = 0.f, x2 = 0.f, x3 = 0.f;
                #pragma unroll
                for (int m = 0; m < 32; m++) {
                    float av = Anx[i4*33 + m];
                    const float4 s = *(const float4*)&sigf[m*32 + jb];
                    x0 += av*s.x; x1 += av*s.y; x2 += av*s.z; x3 += av*s.w;
                }
                T1b[i4*36 + jb]     = x0;
                T1b[i4*36 + jb + 1] = x1;
                T1b[i4*36 + jb + 2] = x2;
                T1b[i4*36 + jb + 3] = x3;
                float4 r = {x0, x1, x2, x3};
                *(float4*)(g_T1s + (size_t)btt*1024 + i4*32 + jb) = r;
            }
            __syncthreads();   // B7

            // B8 phase (tiled): sigp[i4][jb+s] = Q + sum_m T1[i4][m]*Anx[jb+s][m]
            {
                float a0 = (i4 == jb    ) ? 0.08f : 0.f;
                float a1 = (i4 == jb + 1) ? 0.08f : 0.f;
                float a2 = (i4 == jb + 2) ? 0.08f : 0.f;
                float a3 = (i4 == jb + 3) ? 0.08f : 0.f;
                #pragma unroll
                for (int m4 = 0; m4 < 32; m4 += 4) {
                    const float4 t4 = *(const float4*)&T1b[i4*36 + m4];
                    a0 += t4.x*Anx[(jb    )*33 + m4]     + t4.y*Anx[(jb    )*33 + m4 + 1]
                        + t4.z*Anx[(jb    )*33 + m4 + 2] + t4.w*Anx[(jb    )*33 + m4 + 3];
                    a1 += t4.x*Anx[(jb + 1)*33 + m4]     + t4.y*Anx[(jb + 1)*33 + m4 + 1]
                        + t4.z*Anx[(jb + 1)*33 + m4 + 2] + t4.w*Anx[(jb + 1)*33 + m4 + 3];
                    a2 += t4.x*Anx[(jb + 2)*33 + m4]     + t4.y*Anx[(jb + 2)*33 + m4 + 1]
                        + t4.z*Anx[(jb + 2)*33 + m4 + 2] + t4.w*Anx[(jb + 2)*33 + m4 + 3];
                    a3 += t4.x*Anx[(jb + 3)*33 + m4]     + t4.y*Anx[(jb + 3)*33 + m4 + 1]
                        + t4.z*Anx[(jb + 3)*33 + m4 + 2] + t4.w*Anx[(jb + 3)*33 + m4 + 3];
                }
                sigp[i4*33 + jb]     = a0;
                sigp[i4*33 + jb + 1] = a1;
                sigp[i4*33 + jb + 2] = a2;
                sigp[i4*33 + jb + 3] = a3;
                float4 r = {a0, a1, a2, a3};
                *(float4*)(g_sp + (size_t)btt*1024 + i4*32 + jb) = r;
            }
            __syncthreads();   // B8
        }
    }
}

// =====================================================================
// Kernel 4: batched solves X = sp^{-1} T1 — register GJ (round-9
// verified pivot loop) with COALESCED I/O:
//  - left half: sp column c == sp row c (symmetric) -> 2 coalesced
//    float4 loads per thread (perturbation ~1e-7, feeds only the
//    contractive backward pass — safe, unlike the fwd M1 case)
//  - right half: T1 staged coalesced through padded shared (stride 33)
//  - X output staged through the same shared buffer, coalesced stores
// =====================================================================
__global__ void __launch_bounds__(256)
solve_kernel()
{
    const int lin = blockIdx.x;             // 0 .. Bq*(Tq-1)-1
    const int b = lin / (Tq - 1), t = lin % (Tq - 1);
    const size_t bt = (size_t)b*Tq + t;
    const int tid = threadIdx.x;
    const int c = tid >> 2, q = tid & 3;

    __shared__ float Tsh[32*33];
    __shared__ float sfac[2][32];
    __shared__ float spinv[2];

    // stage T1 coalesced -> shared (stride 33; STS conflict-free)
    #pragma unroll
    for (int k = 0; k < 4; k++) {
        int e = tid + 256*k, i = e >> 5, j = e & 31;
        Tsh[i*33 + j] = g_T1s[bt*1024 + e];
    }

    float reg[8];
    if (c < 32) {
        // sp symmetric: column c == row c (contiguous) -> 2 float4 loads
        const float4* bp = (const float4*)(g_sp + bt*1024 + c*32 + q*8);
        float4 r0 = bp[0], r1 = bp[1];
        reg[0] = r0.x; reg[1] = r0.y; reg[2] = r0.z; reg[3] = r0.w;
        reg[4] = r1.x; reg[5] = r1.y; reg[6] = r1.z; reg[7] = r1.w;
    }
    // pivot-0 prep: column 0 snapshot + reciprocal
    if (c == 0) {
        #pragma unroll
        for (int i = 0; i < 8; i++) sfac[0][q*8 + i] = reg[i];
        if (q == 0) spinv[0] = 1.f/reg[0];
    }
    __syncthreads();
    if (c >= 32) {
        // column (c-32) of T1 from padded shared (LDS conflict-free)
        #pragma unroll
        for (int i = 0; i < 8; i++) reg[i] = Tsh[(q*8 + i)*33 + (c - 32)];
    }

    #pragma unroll
    for (int p = 0; p < 32; p++) {
        const int pb = p & 1;
        const float piv = spinv[pb];
        float fac[8];
        #pragma unroll
        for (int i = 0; i < 8; i++) fac[i] = sfac[pb][q*8 + i];
        // row-p element of my column (pre-update), from the lane with q = p>>3
        float m_pc = __shfl_sync(0xffffffffu, reg[p & 7], p >> 3, 4);
        float mn = m_pc * piv;
        if (c > p) {
            #pragma unroll
            for (int i = 0; i < 8; i++) {
                int r = q*8 + i;
                reg[i] = (r == p) ? mn : (reg[i] - fac[i]*mn);
            }
            if (p < 31 && c == p + 1) {
                #pragma unroll
                for (int i = 0; i < 8; i++) sfac[pb ^ 1][q*8 + i] = reg[i];
                if (q == ((p + 1) >> 3)) spinv[pb ^ 1] = 1.f/reg[(p + 1) & 7];
            }
        }
        __syncthreads();
    }

    // stage X through shared (conflict-free STS), write coalesced
    if (c >= 32) {
        #pragma unroll
        for (int i = 0; i < 8; i++) Tsh[(q*8 + i)*33 + (c - 32)] = reg[i];
    }
    __syncthreads();
    #pragma unroll
    for (int k = 0; k < 4; k++) {
        int e = tid + 256*k, i = e >> 5, j = e & 31;
        g_X[bt*1024 + e] = Tsh[i*33 + j];
    }
}

// =====================================================================
// Kernel 5: RTS backward (verified, unchanged).
// =====================================================================
__global__ void __launch_bounds__(256)
bwd_kernel(float* __restrict__ out_mu, float* __restrict__ out_sig)
{
    __shared__ __align__(16) float X[1024], D[1024], G[1024], Ssn[1024];
    __shared__ float sdm[ZD], smf[ZD], sxv[ZD], smusn[ZD];

    const int b = blockIdx.x, tid = threadIdx.x;
    const int i4 = tid >> 3, jb = (tid & 7) << 2;

    {
        const size_t bt = (size_t)b*Tq + (Tq - 1);
        ((float4*)Ssn)[tid] = ((const float4*)(g_sigf + bt*1024))[tid];
        if (tid < ZD) smusn[tid] = g_muf[bt*ZD + tid];
    }
    __syncthreads();

    for (int t = Tq - 2; t >= 0; t--) {
        const size_t bt = (size_t)b*Tq + t;
        // pass0: loads
        ((float4*)X)[tid] = ((const float4*)(g_X + bt*1024))[tid];
        {
            float4 s = ((const float4*)Ssn)[tid];
            float4 p = ((const float4*)(g_sp + bt*1024))[tid];
            float4 d = {s.x - p.x, s.y - p.y, s.z - p.z, s.w - p.w};
            ((float4*)D)[tid] = d;
        }
        if (tid < ZD) {
            sdm[tid] = smusn[tid] - g_mp[bt*ZD + tid];
            smf[tid] = g_muf[bt*ZD + tid];
        }
        __syncthreads();

        // pass A: G = D @ X ; xv = X^T dm
        {
            float g0 = 0, g1 = 0, g2 = 0, g3 = 0;
            #pragma unroll
            for (int m = 0; m < 32; m++) {
                float dv = D[i4*32 + m];
                const float4 xm = *(const float4*)&X[m*32 + jb];
                g0 += dv*xm.x; g1 += dv*xm.y; g2 += dv*xm.z; g3 += dv*xm.w;
            }
            G[i4*32 + jb] = g0; G[i4*32 + jb + 1] = g1;
            G[i4*32 + jb + 2] = g2; G[i4*32 + jb + 3] = g3;
        }
        if (tid < ZD) {
            float v = 0.f;
            #pragma unroll
            for (int k = 0; k < 32; k++) v += X[k*32 + tid]*sdm[k];
            sxv[tid] = v;
        }
        __syncthreads();

        // pass B: sig_s = sf + X^T G ; mu_s = mf + xv
        {
            float4 acc = ((const float4*)(g_sigf + bt*1024))[tid];
            #pragma unroll
            for (int k = 0; k < 32; k++) {
                float xk = X[k*32 + i4];
                const float4 g4 = *(const float4*)&G[k*32 + jb];
                acc.x += xk*g4.x; acc.y += xk*g4.y; acc.z += xk*g4.z; acc.w += xk*g4.w;
            }
            ((float4*)(out_sig + bt*1024))[tid] = acc;
            ((float4*)Ssn)[tid] = acc;
        }
        if (tid < ZD) {
            float v = smf[tid] + sxv[tid];
            out_mu[bt*ZD + tid] = v;
            smusn[tid] = v;
        }
        __syncthreads();
    }
}

// =====================================================================
extern "C" void kernel_launch(void* const* d_in, const int* in_sizes, int n_in,
                              void* d_out, int out_size)
{
    const float* a       = (const float*)d_in[0];
    const float* a1      = (const float*)d_in[1];
    const float* W_ih    = (const float*)d_in[2];
    const float* W_hh    = (const float*)d_in[3];
    const float* b_ih    = (const float*)d_in[4];
    const float* b_hh    = (const float*)d_in[5];
    const float* W_alpha = (const float*)d_in[6];
    const float* b_alpha = (const float*)d_in[7];
    const float* Ag      = (const float*)d_in[8];
    const float* Cg      = (const float*)d_in[9];

    float* out    = (float*)d_out;
    float* out_mu = out;                              // [B,T,32]
    float* out_sg = out_mu + (size_t)BT*ZD;           // [B,T,32,32]
    float* out_A  = out_sg + (size_t)BT*ZD*ZD;        // [B,T,32,32]
    float* out_C  = out_A  + (size_t)BT*ZD*ZD;        // [B,T,8,32]

    lstm_kernel<<<Bq, 256>>>(a, a1, W_ih, W_hh, b_ih, b_hh, W_alpha, b_alpha);
    mix_kernel<<<BT/128, 256>>>(Ag, Cg, out_A, out_C);
    fwd_kernel<<<Bq, 256>>>(a, out_mu, out_sg, out_A, out_C);
    solve_kernel<<<Bq*(Tq - 1), 256>>>();
    bwd_kernel<<<Bq, 256>>>(out_mu, out_sg);
}